// round 5
// baseline (speedup 1.0000x reference)
#include <cuda_runtime.h>
#include <cuda_bf16.h>
#include <cstdint>
#include <math.h>

#define NT 4096
#define ND 1024
#define NE 8
#define NF 2048
#define N2F 4096

// tcgen05 availability: only in the 'a'-suffix front-end passes
#if defined(__CUDA_ARCH_FEAT_SM103_ALL) || defined(__CUDA_ARCH_FEAT_SM100_ALL)
#define TC_OK 1
#else
#define TC_OK 0
#endif

typedef unsigned long long ull;

// ---------------- scratch (no allocs allowed) ----------------
__device__ int      g_cnt[NE];
__device__ int      g_tok[NE * NT];
__device__ float    g_wt[NT * 2];
__device__ int      g_slot[NT * 2];
__device__ int      g_eid[NT * 2];
__device__ uint32_t g_hidden_pk[(size_t)NE * NT * NF]; // tc: bf16 hi|lo pack; simt: fp32
__device__ float    g_y[(size_t)NE * NT * ND];
// pre-split weights: SMEM-image blocks of 8KB (64 n-rows x 64 k bf16, SW128)
// layout: [e][nsub][plane(hi/lo)][kc][512 x uint4]
__device__ uint4    g_w1s[(size_t)NE * 64 * 2 * 16 * 512]; // 128 MB
__device__ uint4    g_w2s[(size_t)NE * 16 * 2 * 32 * 512]; //  64 MB

// ---------------- generic helpers ----------------
__device__ __forceinline__ uint32_t smem_u32(const void* p) {
    uint32_t a;
    asm("{ .reg .u64 t; cvta.to.shared.u64 t, %1; cvt.u32.u64 %0, t; }" : "=r"(a) : "l"(p));
    return a;
}
__device__ __forceinline__ uint32_t elect1() {
    uint32_t r;
    asm volatile("{ .reg .pred p; elect.sync _|p, 0xFFFFFFFF; selp.b32 %0,1,0,p; }" : "=r"(r));
    return r;
}
#define MBAR_INIT(a, c) asm volatile("mbarrier.init.shared.b64 [%0], %1;" :: "r"(a), "r"(c) : "memory")
#define MBAR_INVAL(a)   asm volatile("mbarrier.inval.shared.b64 [%0];" :: "r"(a) : "memory")
#define MBAR_WAIT(a, ph) do { uint32_t _m=(a); uint32_t _p=(ph); uint32_t _d;                               \
    asm volatile("{ .reg .pred p; mbarrier.try_wait.parity.acquire.cta.shared::cta.b64 p,[%1],%2; "        \
                 "selp.b32 %0,1,0,p; }" : "=r"(_d) : "r"(_m), "r"(_p) : "memory");                          \
    if (!_d) { asm volatile("{ .reg .pred P1; WL%=: "                                                      \
        "mbarrier.try_wait.parity.acquire.cta.shared::cta.b64 P1,[%0],%1,0x989680; "                       \
        "@P1 bra.uni WD%=; bra.uni WL%=; WD%=: }" :: "r"(_m), "r"(_p) : "memory"); } } while (0)
#define FENCE_ASYNC() asm volatile("fence.proxy.async.shared::cta;" ::: "memory")

// SW128 swizzle (tile-relative; tile bases 1024-aligned)
#define SWZ(x) ((x) ^ (((x) >> 3) & 0x70))

// ---------------- tcgen05-only macros/helpers ----------------
#if TC_OK
#define TCG_ALLOC(sa, n)  asm volatile("tcgen05.alloc.cta_group::1.sync.aligned.shared::cta.b32 [%0], %1;" :: "r"(sa), "r"(n) : "memory")
#define TCG_DEALLOC(t, n) asm volatile("tcgen05.dealloc.cta_group::1.sync.aligned.b32 %0, %1;" :: "r"(t), "r"(n))
#define TCG_RELINQ()      asm volatile("tcgen05.relinquish_alloc_permit.cta_group::1.sync.aligned;")
#define TCG_COMMIT(a)     asm volatile("tcgen05.commit.cta_group::1.mbarrier::arrive::one.shared::cluster.b64 [%0];" :: "r"(a) : "memory")
#define TCG_FENCE_AFTER()  asm volatile("tcgen05.fence::after_thread_sync;" ::: "memory")
#define TCG_FENCE_BEFORE() asm volatile("tcgen05.fence::before_thread_sync;" ::: "memory")
#define TCG_WAIT_LD()      asm volatile("tcgen05.wait::ld.sync.aligned;" ::: "memory")

#define TCG_LD32(r, ta) \
    asm volatile("tcgen05.ld.sync.aligned.32x32b.x32.b32 " \
        "{%0,%1,%2,%3,%4,%5,%6,%7,%8,%9,%10,%11,%12,%13,%14,%15," \
        "%16,%17,%18,%19,%20,%21,%22,%23,%24,%25,%26,%27,%28,%29,%30,%31}, [%32];" \
        : "=r"((r)[0]),"=r"((r)[1]),"=r"((r)[2]),"=r"((r)[3]),"=r"((r)[4]),"=r"((r)[5]),"=r"((r)[6]),"=r"((r)[7]), \
          "=r"((r)[8]),"=r"((r)[9]),"=r"((r)[10]),"=r"((r)[11]),"=r"((r)[12]),"=r"((r)[13]),"=r"((r)[14]),"=r"((r)[15]), \
          "=r"((r)[16]),"=r"((r)[17]),"=r"((r)[18]),"=r"((r)[19]),"=r"((r)[20]),"=r"((r)[21]),"=r"((r)[22]),"=r"((r)[23]), \
          "=r"((r)[24]),"=r"((r)[25]),"=r"((r)[26]),"=r"((r)[27]),"=r"((r)[28]),"=r"((r)[29]),"=r"((r)[30]),"=r"((r)[31]) \
        : "r"(ta))

__device__ __forceinline__ uint64_t descK(uint32_t a) {   // K-major SW128: LBO=1, SBO=64
    return ((uint64_t)2 << 61) | ((uint64_t)1 << 46) | ((uint64_t)64 << 32) |
           ((uint64_t)1 << 16) | ((a >> 4) & 0x3FFF);
}
// kind::f16 idesc: dtype=F32, atype=btype=BF16, both K-major, N=64, M=128
#define IDESC_BF16 ((1u<<4) | (1u<<7) | (1u<<10) | (8u<<17) | (8u<<24))

__device__ __forceinline__ void mma_bf16(uint32_t d, uint64_t ad, uint64_t bd, uint32_t en) {
    asm volatile("{ .reg .pred p; setp.ne.u32 p, %4, 0;\n\t"
        "tcgen05.mma.cta_group::1.kind::f16 [%0], %1, %2, %3, {%5,%5,%5,%5}, p; }"
        :: "r"(d), "l"(ad), "l"(bd), "r"(IDESC_BF16), "r"(en), "r"(0u) : "memory");
}
#endif // TC_OK

// pack two fp32 -> bf16x2 (h -> high half, l -> low half)
__device__ __forceinline__ uint32_t bf2(float h, float l) {
    uint32_t r; asm("cvt.rn.bf16x2.f32 %0, %1, %2;" : "=r"(r) : "f"(h), "f"(l)); return r;
}
// split 8 fp32 into hi(trunc top-16, exact bf16) and lo(bf16_rn of residual)
__device__ __forceinline__ void split8(float4 v0, float4 v1, uint4& hi, uint4& lo) {
    uint32_t u0 = __float_as_uint(v0.x), u1 = __float_as_uint(v0.y);
    uint32_t u2 = __float_as_uint(v0.z), u3 = __float_as_uint(v0.w);
    uint32_t u4 = __float_as_uint(v1.x), u5 = __float_as_uint(v1.y);
    uint32_t u6 = __float_as_uint(v1.z), u7 = __float_as_uint(v1.w);
    hi.x = __byte_perm(u0, u1, 0x7632); hi.y = __byte_perm(u2, u3, 0x7632);
    hi.z = __byte_perm(u4, u5, 0x7632); hi.w = __byte_perm(u6, u7, 0x7632);
    float l0 = v0.x - __uint_as_float(u0 & 0xffff0000u);
    float l1 = v0.y - __uint_as_float(u1 & 0xffff0000u);
    float l2 = v0.z - __uint_as_float(u2 & 0xffff0000u);
    float l3 = v0.w - __uint_as_float(u3 & 0xffff0000u);
    float l4 = v1.x - __uint_as_float(u4 & 0xffff0000u);
    float l5 = v1.y - __uint_as_float(u5 & 0xffff0000u);
    float l6 = v1.z - __uint_as_float(u6 & 0xffff0000u);
    float l7 = v1.w - __uint_as_float(u7 & 0xffff0000u);
    lo.x = bf2(l1, l0); lo.y = bf2(l3, l2); lo.z = bf2(l5, l4); lo.w = bf2(l7, l6);
}

// packed f32x2 (SIMT fallback)
__device__ __forceinline__ ull packf2(float x, float y) {
    ull u; asm("mov.b64 %0,{%1,%2};" : "=l"(u) : "f"(x), "f"(y)); return u;
}
__device__ __forceinline__ float2 unpk(ull u) {
    float2 r; asm("mov.b64 {%0,%1},%2;" : "=f"(r.x), "=f"(r.y) : "l"(u)); return r;
}
__device__ __forceinline__ ull fma2(ull a, ull b, ull c) {
    ull d; asm("fma.rn.f32x2 %0, %1, %2, %3;" : "=l"(d) : "l"(a), "l"(b), "l"(c)); return d;
}

// SMEM stage layout: A_hi 16K | A_lo 16K | B_hi 4x8K | B_lo 4x8K
#define ST_AHI   0
#define ST_ALO   16384
#define ST_BHI   32768
#define ST_BLO   65536
#define ST_SIZE  98304
#define DYNSMEM  (2 * ST_SIZE + 2048)

// ======================= kernel 0: zero counters =======================
__global__ void zero_cnt_kernel() {
    if (threadIdx.x < NE) g_cnt[threadIdx.x] = 0;
}

// ======================= kernel 1: router =======================
__global__ void router_kernel(const float* __restrict__ x,
                              const float* __restrict__ Wr,
                              const float* __restrict__ temp) {
    int t    = (blockIdx.x * blockDim.x + threadIdx.x) >> 5;
    int lane = threadIdx.x & 31;
    if (t >= NT) return;
    const float* xr = x + (size_t)t * ND;
    float acc[NE];
#pragma unroll
    for (int e = 0; e < NE; e++) acc[e] = 0.f;
    for (int d = lane; d < ND; d += 32) {
        float xv = xr[d];
        const float* wr = Wr + d * NE;
#pragma unroll
        for (int e = 0; e < NE; e++) acc[e] = fmaf(xv, wr[e], acc[e]);
    }
#pragma unroll
    for (int e = 0; e < NE; e++) {
#pragma unroll
        for (int off = 16; off > 0; off >>= 1)
            acc[e] += __shfl_xor_sync(0xffffffffu, acc[e], off);
    }
    if (lane == 0) {
        float ti = 1.0f / temp[0];
#pragma unroll
        for (int e = 0; e < NE; e++) acc[e] *= ti;
        int i0 = 0; float l0 = acc[0];
#pragma unroll
        for (int e = 1; e < NE; e++) if (acc[e] > l0) { l0 = acc[e]; i0 = e; }
        int i1 = -1; float l1 = -3.4e38f;
#pragma unroll
        for (int e = 0; e < NE; e++)
            if (e != i0 && acc[e] > l1) { l1 = acc[e]; i1 = e; }
        float ex  = expf(l1 - l0);
        float w1v = ex / (1.f + ex);
        float w0v = 1.f - w1v;
        int p0 = atomicAdd(&g_cnt[i0], 1);
        int p1 = atomicAdd(&g_cnt[i1], 1);
        g_tok[i0 * NT + p0] = t;
        g_tok[i1 * NT + p1] = t;
        g_slot[2 * t]     = i0 * NT + p0;
        g_slot[2 * t + 1] = i1 * NT + p1;
        g_wt[2 * t]     = w0v;
        g_wt[2 * t + 1] = w1v;
        g_eid[2 * t]     = i0;
        g_eid[2 * t + 1] = i1;
    }
}

// ======================= weight prepass: W1 -> g_w1s =======================
// one CTA per (kc, nsub, e): builds 8KB hi + 8KB lo SMEM-image blocks
__global__ __launch_bounds__(128) void prep_w1(const float* __restrict__ W1) {
#if TC_OK
    int kc = blockIdx.x;   // 0..15
    int nsub = blockIdx.y; // 0..63 (0..31 = a-half, 32..63 = g-half)
    int e = blockIdx.z;
    int tid = threadIdx.x;
    int n = tid & 63;
    int kb2 = tid >> 6;    // 0..1
    int col = (nsub < 32) ? (nsub * 64 + n) : (NF + (nsub - 32) * 64 + n);
    const float* gc = W1 + (size_t)e * ND * N2F + (size_t)(kc * 64) * N2F + col;
    size_t blkHi = ((((size_t)e * 64 + nsub) * 2 + 0) * 16 + kc) * 512;
    size_t blkLo = ((((size_t)e * 64 + nsub) * 2 + 1) * 16 + kc) * 512;
#pragma unroll
    for (int it = 0; it < 4; it++) {
        int kb = kb2 + it * 2;
        float4 v0, v1;
        v0.x = gc[(size_t)(kb * 8 + 0) * N2F];
        v0.y = gc[(size_t)(kb * 8 + 1) * N2F];
        v0.z = gc[(size_t)(kb * 8 + 2) * N2F];
        v0.w = gc[(size_t)(kb * 8 + 3) * N2F];
        v1.x = gc[(size_t)(kb * 8 + 4) * N2F];
        v1.y = gc[(size_t)(kb * 8 + 5) * N2F];
        v1.z = gc[(size_t)(kb * 8 + 6) * N2F];
        v1.w = gc[(size_t)(kb * 8 + 7) * N2F];
        uint4 hi, lo; split8(v0, v1, hi, lo);
        uint32_t off = SWZ((uint32_t)(n * 128 + kb * 16)) >> 4;
        g_w1s[blkHi + off] = hi;
        g_w1s[blkLo + off] = lo;
    }
#endif
}

// ======================= weight prepass: W2 -> g_w2s =======================
__global__ __launch_bounds__(128) void prep_w2(const float* __restrict__ W2) {
#if TC_OK
    int kc = blockIdx.x;   // 0..31
    int nsub = blockIdx.y; // 0..15
    int e = blockIdx.z;
    int tid = threadIdx.x;
    int n = tid & 63;
    int kb2 = tid >> 6;
    int col = nsub * 64 + n;
    const float* gc = W2 + (size_t)e * NF * ND + (size_t)(kc * 64) * ND + col;
    size_t blkHi = ((((size_t)e * 16 + nsub) * 2 + 0) * 32 + kc) * 512;
    size_t blkLo = ((((size_t)e * 16 + nsub) * 2 + 1) * 32 + kc) * 512;
#pragma unroll
    for (int it = 0; it < 4; it++) {
        int kb = kb2 + it * 2;
        float4 v0, v1;
        v0.x = gc[(size_t)(kb * 8 + 0) * ND];
        v0.y = gc[(size_t)(kb * 8 + 1) * ND];
        v0.z = gc[(size_t)(kb * 8 + 2) * ND];
        v0.w = gc[(size_t)(kb * 8 + 3) * ND];
        v1.x = gc[(size_t)(kb * 8 + 4) * ND];
        v1.y = gc[(size_t)(kb * 8 + 5) * ND];
        v1.z = gc[(size_t)(kb * 8 + 6) * ND];
        v1.w = gc[(size_t)(kb * 8 + 7) * ND];
        uint4 hi, lo; split8(v0, v1, hi, lo);
        uint32_t off = SWZ((uint32_t)(n * 128 + kb * 16)) >> 4;
        g_w2s[blkHi + off] = hi;
        g_w2s[blkLo + off] = lo;
    }
#endif
}

// ======================= tcgen05 GEMM1 + SwiGLU =======================
// M-tile 128 gathered rows; N: 128 a-cols + paired 128 g-cols; K=1024, 16 chunks of 64.
__global__ __launch_bounds__(256, 1) void gemm1_tc(
        const float* __restrict__ x,
        const float* __restrict__ b1) {
#if TC_OK
    int e    = blockIdx.z;
    int cnt  = g_cnt[e];
    int row0 = blockIdx.x * 128;
    if (row0 >= cnt) return;
    int na0 = blockIdx.y * 128;
    int nb  = na0 >> 6;

    extern __shared__ char dynsmem[];
    uint32_t raw   = smem_u32(dynsmem);
    uint32_t base  = (raw + 1023) & ~1023u;
    uint32_t hdr   = base;
    uint32_t data0 = base + 1024;
    char* pdata = dynsmem + (data0 - raw);

    int tid = threadIdx.x, wid = tid >> 5, lane = tid & 31;

    if (tid == 0) { MBAR_INIT(hdr + 8, 1); MBAR_INIT(hdr + 16, 1); }
    if (wid == 0) { TCG_ALLOC(hdr, 256); }
    __syncthreads();
    uint32_t tmem;
    asm("ld.shared.b32 %0, [%1];" : "=r"(tmem) : "r"(hdr));

    // gathered A row pointers (rows rb + 32*it)
    const float* aptr[4];
    {
        int rb = tid >> 3;
#pragma unroll
        for (int it = 0; it < 4; it++) {
            int rr = row0 + rb + 32 * it;
            if (rr >= cnt) rr = cnt - 1;
            aptr[it] = x + (size_t)g_tok[e * NT + rr] * ND;
        }
    }

    int ph0 = 0, ph1 = 0;
    const int CH = ND / 64; // 16
    for (int c = 0; c < CH; c++) {
        int b = c & 1;
        uint32_t st = data0 + b * ST_SIZE;
        char* sp = pdata + b * ST_SIZE;
        if (c >= 2) {
            if (b == 0) { MBAR_WAIT(hdr + 8,  ph0 & 1); ph0++; }
            else        { MBAR_WAIT(hdr + 16, ph1 & 1); ph1++; }
        }
        int k0 = c * 64;
        // A (128 rows x 64 k), gather + split
        {
            int kq = (tid & 7) * 8;
            int rb = tid >> 3;
#pragma unroll
            for (int it = 0; it < 4; it++) {
                int r = rb + 32 * it;
                const float* p = aptr[it] + k0 + kq;
                float4 v0 = *(const float4*)p;
                float4 v1 = *(const float4*)(p + 4);
                uint4 hi, lo; split8(v0, v1, hi, lo);
                uint32_t off = SWZ((uint32_t)(r * 128 + kq * 2));
                *(uint4*)(sp + ST_AHI + off) = hi;
                *(uint4*)(sp + ST_ALO + off) = lo;
            }
        }
        // B: verbatim copy of pre-split 8KB blocks (4 nsub x hi/lo)
        {
            int boff = tid * 2;
#pragma unroll
            for (int s = 0; s < 4; s++) {
                int nsub = (s < 2) ? (nb + s) : (32 + nb + (s - 2));
                const uint4* srcHi = g_w1s + ((((size_t)e * 64 + nsub) * 2 + 0) * 16 + c) * 512;
                const uint4* srcLo = g_w1s + ((((size_t)e * 64 + nsub) * 2 + 1) * 16 + c) * 512;
                uint4* dstHi = (uint4*)(sp + ST_BHI + s * 8192);
                uint4* dstLo = (uint4*)(sp + ST_BLO + s * 8192);
                dstHi[boff]     = srcHi[boff];
                dstHi[boff + 1] = srcHi[boff + 1];
                dstLo[boff]     = srcLo[boff];
                dstLo[boff + 1] = srcLo[boff + 1];
            }
        }
        FENCE_ASYNC();
        __syncthreads();
        if (wid == 0 && elect1()) {
            uint64_t dA[3] = { descK(st + ST_AHI), descK(st + ST_AHI), descK(st + ST_ALO) };
            uint32_t bOff[3] = { ST_BHI, ST_BLO, ST_BHI };
#pragma unroll
            for (int pi = 0; pi < 3; pi++) {
#pragma unroll
                for (int ks = 0; ks < 4; ks++) {
                    uint32_t en = (c > 0 || pi > 0 || ks > 0) ? 1u : 0u;
#pragma unroll
                    for (int nt = 0; nt < 4; nt++) {
                        uint64_t bd = descK(st + bOff[pi] + nt * 8192) + (uint64_t)(ks * 2);
                        mma_bf16(tmem + nt * 64, dA[pi] + (uint64_t)(ks * 2), bd, en);
                    }
                }
            }
            TCG_COMMIT(b == 0 ? hdr + 8 : hdr + 16);
        }
    }
    {
        int b = (CH - 1) & 1;
        if (b == 0) { MBAR_WAIT(hdr + 8,  ph0 & 1); }
        else        { MBAR_WAIT(hdr + 16, ph1 & 1); }
    }
    TCG_FENCE_AFTER();
    // epilogue: warps 0-3 cols 0..63, warps 4-7 cols 64..127 (same rows by w&3)
    int row = row0 + (wid & 3) * 32 + lane;
    bool act = row < cnt;
    const float* b1a = b1 + (size_t)e * N2F + na0;
    const float* b1g = b1 + (size_t)e * N2F + NF + na0;
    int j0 = (wid >> 2) * 2;
    for (int jj = j0; jj < j0 + 2; jj++) {
        uint32_t ar[32], gr[32];
        TCG_LD32(ar, tmem + jj * 32);
        TCG_LD32(gr, tmem + 128 + jj * 32);
        TCG_WAIT_LD();
        if (act) {
            uint32_t pk[32];
#pragma unroll
            for (int q = 0; q < 32; q++) {
                float av = __uint_as_float(ar[q]) + b1a[jj * 32 + q];
                float gv = __uint_as_float(gr[q]) + b1g[jj * 32 + q];
                float hv = av * (gv / (1.f + __expf(-gv)));
                uint32_t u = __float_as_uint(hv);
                float lof = hv - __uint_as_float(u & 0xffff0000u);
                uint16_t lob = __bfloat16_as_ushort(__float2bfloat16(lof));
                pk[q] = (u >> 16) | ((uint32_t)lob << 16);
            }
            uint32_t* dst = g_hidden_pk + ((size_t)e * NT + row) * NF + na0 + jj * 32;
#pragma unroll
            for (int q = 0; q < 8; q++) *(uint4*)(dst + 4 * q) = *(uint4*)&pk[4 * q];
        }
    }
    TCG_FENCE_BEFORE();
    __syncthreads();
    if (tid == 0) { MBAR_INVAL(hdr + 8); MBAR_INVAL(hdr + 16); }
    if (wid == 0) { TCG_RELINQ(); TCG_DEALLOC(tmem, 256); }
#endif
}

// ======================= tcgen05 GEMM2 =======================
// M-tile 128 compact rows; N-tile 256 of d_model; K=2048, 32 chunks of 64.
__global__ __launch_bounds__(256, 1) void gemm2_tc() {
#if TC_OK
    int e    = blockIdx.z;
    int cnt  = g_cnt[e];
    int row0 = blockIdx.x * 128;
    if (row0 >= cnt) return;
    int n0 = blockIdx.y * 256;
    int nb = n0 >> 6;

    extern __shared__ char dynsmem[];
    uint32_t raw   = smem_u32(dynsmem);
    uint32_t base  = (raw + 1023) & ~1023u;
    uint32_t hdr   = base;
    uint32_t data0 = base + 1024;
    char* pdata = dynsmem + (data0 - raw);

    int tid = threadIdx.x, wid = tid >> 5, lane = tid & 31;

    if (tid == 0) { MBAR_INIT(hdr + 8, 1); MBAR_INIT(hdr + 16, 1); }
    if (wid == 0) { TCG_ALLOC(hdr, 256); }
    __syncthreads();
    uint32_t tmem;
    asm("ld.shared.b32 %0, [%1];" : "=r"(tmem) : "r"(hdr));

    const uint32_t* hptr[4];
    {
        int rb = tid >> 3;
#pragma unroll
        for (int it = 0; it < 4; it++) {
            int rr = row0 + rb + 32 * it;
            if (rr >= cnt) rr = cnt - 1;
            hptr[it] = g_hidden_pk + ((size_t)e * NT + rr) * NF;
        }
    }

    int ph0 = 0, ph1 = 0;
    const int CH = NF / 64; // 32
    for (int c = 0; c < CH; c++) {
        int b = c & 1;
        uint32_t st = data0 + b * ST_SIZE;
        char* sp = pdata + b * ST_SIZE;
        if (c >= 2) {
            if (b == 0) { MBAR_WAIT(hdr + 8,  ph0 & 1); ph0++; }
            else        { MBAR_WAIT(hdr + 16, ph1 & 1); ph1++; }
        }
        int k0 = c * 64;
        // A from packed hidden (already bf16 hi/lo)
        {
            int kq = (tid & 7) * 8;
            int rb = tid >> 3;
#pragma unroll
            for (int it = 0; it < 4; it++) {
                int r = rb + 32 * it;
                const uint32_t* p = hptr[it] + k0 + kq;
                uint4 w0 = *(const uint4*)p;
                uint4 w1 = *(const uint4*)(p + 4);
                uint4 hi, lo;
                hi.x = __byte_perm(w0.x, w0.y, 0x5410); lo.x = __byte_perm(w0.x, w0.y, 0x7632);
                hi.y = __byte_perm(w0.z, w0.w, 0x5410); lo.y = __byte_perm(w0.z, w0.w, 0x7632);
                hi.z = __byte_perm(w1.x, w1.y, 0x5410); lo.z = __byte_perm(w1.x, w1.y, 0x7632);
                hi.w = __byte_perm(w1.z, w1.w, 0x5410); lo.w = __byte_perm(w1.z, w1.w, 0x7632);
                uint32_t off = SWZ((uint32_t)(r * 128 + kq * 2));
                *(uint4*)(sp + ST_AHI + off) = hi;
                *(uint4*)(sp + ST_ALO + off) = lo;
            }
        }
        // B verbatim copy from pre-split blocks
        {
            int boff = tid * 2;
#pragma unroll
            for (int s = 0; s < 4; s++) {
                int nsub = nb + s;
                const uint4* srcHi = g_w2s + ((((size_t)e * 16 + nsub) * 2 + 0) * 32 + c) * 512;
                const uint4* srcLo = g_w2s + ((((size_t)e * 16 + nsub) * 2 + 1) * 32 + c) * 512;
                uint4* dstHi = (uint4*)(sp + ST_BHI + s * 8192);
                uint4* dstLo = (uint4*)(sp + ST_BLO + s * 8192);
                dstHi[boff]     = srcHi[boff];
                dstHi[boff + 1] = srcHi[boff + 1];
                dstLo[boff]     = srcLo[boff];
                dstLo[boff + 1] = srcLo[boff + 1];
            }
        }
        FENCE_ASYNC();
        __syncthreads();
        if (wid == 0 && elect1()) {
            uint64_t dA[3] = { descK(st + ST_AHI), descK(st + ST_AHI), descK(st + ST_ALO) };
            uint32_t bOff[3] = { ST_BHI, ST_BLO, ST_BHI };
#pragma unroll
            for (int pi = 0; pi < 3; pi++) {
#pragma unroll
                for (int ks = 0; ks < 4; ks++) {
                    uint32_t en = (c > 0 || pi > 0 || ks > 0) ? 1u : 0u;
#pragma unroll
                    for (int nt = 0; nt < 4; nt++) {
                        uint64_t bd = descK(st + bOff[pi] + nt * 8192) + (uint64_t)(ks * 2);
                        mma_bf16(tmem + nt * 64, dA[pi] + (uint64_t)(ks * 2), bd, en);
                    }
                }
            }
            TCG_COMMIT(b == 0 ? hdr + 8 : hdr + 16);
        }
    }
    {
        int b = (CH - 1) & 1;
        if (b == 0) { MBAR_WAIT(hdr + 8,  ph0 & 1); }
        else        { MBAR_WAIT(hdr + 16, ph1 & 1); }
    }
    TCG_FENCE_AFTER();
    int row = row0 + (wid & 3) * 32 + lane;
    bool act = row < cnt;
    int j0 = (wid >> 2) * 4;
    for (int j = j0; j < j0 + 4; j++) {
        uint32_t yr[32];
        TCG_LD32(yr, tmem + j * 32);
        TCG_WAIT_LD();
        if (act) {
            float* dst = g_y + ((size_t)e * NT + row) * ND + n0 + j * 32;
#pragma unroll
            for (int q = 0; q < 8; q++) *(uint4*)(dst + 4 * q) = *(uint4*)&yr[4 * q];
        }
    }
    TCG_FENCE_BEFORE();
    __syncthreads();
    if (tid == 0) { MBAR_INVAL(hdr + 8); MBAR_INVAL(hdr + 16); }
    if (wid == 0) { TCG_RELINQ(); TCG_DEALLOC(tmem, 256); }
#endif
}

// ======================= SIMT fallback GEMM1 + SwiGLU (expert loop inside) =======================
__global__ __launch_bounds__(256) void gemm1_simt(
        const float* __restrict__ x,
        const float* __restrict__ W1,
        const float* __restrict__ b1) {
#if !TC_OK
    __shared__ __align__(16) float As[64][16];
    __shared__ __align__(16) float BsA[16][64];
    __shared__ __align__(16) float BsG[16][64];
    int row0 = blockIdx.x * 64;
    int col0 = blockIdx.y * 64;
    int tid = threadIdx.x;
    int tx = tid & 15, ty = tid >> 4;
    int ra = tid >> 2, qa = tid & 3;
    int kb = tid >> 4, qb = tid & 15;

    for (int e = 0; e < NE; e++) {
        int cnt = g_cnt[e];
        if (row0 >= cnt) continue;
        int rowa = row0 + ra;
        if (rowa >= cnt) rowa = cnt - 1;
        int tok = g_tok[e * NT + rowa];
        const float* xrow = x + (size_t)tok * ND;
        const float* W1e = W1 + (size_t)e * ND * N2F;

        ull accA[4][2], accG[4][2];
#pragma unroll
        for (int r = 0; r < 4; r++)
#pragma unroll
            for (int c = 0; c < 2; c++) { accA[r][c] = 0ull; accG[r][c] = 0ull; }

        for (int k0 = 0; k0 < ND; k0 += 16) {
            float4 av = *(const float4*)(xrow + k0 + qa * 4);
            const float* brow = W1e + (size_t)(k0 + kb) * N2F + col0;
            float4 bA = *(const float4*)(brow + qb * 4);
            float4 bG = *(const float4*)(brow + NF + qb * 4);
            __syncthreads();
            *(float4*)&As[ra][qa * 4]  = av;
            *(float4*)&BsA[kb][qb * 4] = bA;
            *(float4*)&BsG[kb][qb * 4] = bG;
            __syncthreads();
#pragma unroll
            for (int kk = 0; kk < 16; kk++) {
                float4 fA = *(const float4*)&BsA[kk][tx * 4];
                float4 fG = *(const float4*)&BsG[kk][tx * 4];
                ull bA0 = packf2(fA.x, fA.y), bA1 = packf2(fA.z, fA.w);
                ull bG0 = packf2(fG.x, fG.y), bG1 = packf2(fG.z, fG.w);
#pragma unroll
                for (int r = 0; r < 4; r++) {
                    float a = As[ty * 4 + r][kk];
                    ull aa = packf2(a, a);
                    accA[r][0] = fma2(aa, bA0, accA[r][0]);
                    accA[r][1] = fma2(aa, bA1, accA[r][1]);
                    accG[r][0] = fma2(aa, bG0, accG[r][0]);
                    accG[r][1] = fma2(aa, bG1, accG[r][1]);
                }
            }
        }
        float bvA[4], bvG[4];
#pragma unroll
        for (int c = 0; c < 4; c++) {
            bvA[c] = b1[(size_t)e * N2F + col0 + tx * 4 + c];
            bvG[c] = b1[(size_t)e * N2F + NF + col0 + tx * 4 + c];
        }
        float* ghid = (float*)g_hidden_pk;
#pragma unroll
        for (int r = 0; r < 4; r++) {
            int row = row0 + ty * 4 + r;
            if (row >= cnt) continue;
            float2 a0 = unpk(accA[r][0]), a1 = unpk(accA[r][1]);
            float2 g0 = unpk(accG[r][0]), g1 = unpk(accG[r][1]);
            float avv[4] = {a0.x, a0.y, a1.x, a1.y};
            float gvv[4] = {g0.x, g0.y, g1.x, g1.y};
            float4 hout; float* hp = (float*)&hout;
#pragma unroll
            for (int c = 0; c < 4; c++) {
                float aval = avv[c] + bvA[c];
                float gval = gvv[c] + bvG[c];
                hp[c] = aval * (gval / (1.f + expf(-gval)));
            }
            *(float4*)(ghid + ((size_t)e * NT + row) * NF + col0 + tx * 4) = hout;
        }
        __syncthreads();
    }
#endif
}

// ======================= SIMT fallback GEMM2 (expert loop inside) =======================
__global__ __launch_bounds__(256) void gemm2_simt(const float* __restrict__ W2) {
#if !TC_OK
    __shared__ __align__(16) float As[64][16];
    __shared__ __align__(16) float Bs[16][128];
    int row0 = blockIdx.x * 64;
    int col0 = blockIdx.y * 128;
    int tid = threadIdx.x;
    int tx = tid & 15, ty = tid >> 4;
    int ra = tid >> 2, qa = tid & 3;
    int s0i = tid,       kb0 = s0i >> 5, qb0 = s0i & 31;
    int s1i = tid + 256, kb1 = s1i >> 5, qb1 = s1i & 31;

    for (int e = 0; e < NE; e++) {
        int cnt = g_cnt[e];
        if (row0 >= cnt) continue;
        int rowa = row0 + ra;
        if (rowa >= cnt) rowa = cnt - 1;
        const float* ghid = (const float*)g_hidden_pk;
        const float* hrow = ghid + ((size_t)e * NT + rowa) * NF;
        const float* W2e  = W2 + (size_t)e * NF * ND;

        ull acc[4][4];
#pragma unroll
        for (int r = 0; r < 4; r++)
#pragma unroll
            for (int c = 0; c < 4; c++) acc[r][c] = 0ull;

        for (int k0 = 0; k0 < NF; k0 += 16) {
            float4 av  = *(const float4*)(hrow + k0 + qa * 4);
            float4 bv0 = *(const float4*)(W2e + (size_t)(k0 + kb0) * ND + col0 + qb0 * 4);
            float4 bv1 = *(const float4*)(W2e + (size_t)(k0 + kb1) * ND + col0 + qb1 * 4);
            __syncthreads();
            *(float4*)&As[ra][qa * 4]   = av;
            *(float4*)&Bs[kb0][qb0 * 4] = bv0;
            *(float4*)&Bs[kb1][qb1 * 4] = bv1;
            __syncthreads();
#pragma unroll
            for (int kk = 0; kk < 16; kk++) {
                float4 f0 = *(const float4*)&Bs[kk][tx * 8];
                float4 f1 = *(const float4*)&Bs[kk][tx * 8 + 4];
                ull b0 = packf2(f0.x, f0.y), b1p = packf2(f0.z, f0.w);
                ull b2p = packf2(f1.x, f1.y), b3p = packf2(f1.z, f1.w);
#pragma unroll
                for (int r = 0; r < 4; r++) {
                    float a = As[ty * 4 + r][kk];
                    ull aa = packf2(a, a);
                    acc[r][0] = fma2(aa, b0,  acc[r][0]);
                    acc[r][1] = fma2(aa, b1p, acc[r][1]);
                    acc[r][2] = fma2(aa, b2p, acc[r][2]);
                    acc[r][3] = fma2(aa, b3p, acc[r][3]);
                }
            }
        }
#pragma unroll
        for (int r = 0; r < 4; r++) {
            int row = row0 + ty * 4 + r;
            if (row >= cnt) continue;
            float* yp = g_y + ((size_t)e * NT + row) * ND + col0 + tx * 8;
            float2 v0 = unpk(acc[r][0]), v1 = unpk(acc[r][1]);
            float2 v2 = unpk(acc[r][2]), v3 = unpk(acc[r][3]);
            float4 o0 = {v0.x, v0.y, v1.x, v1.y};
            float4 o1 = {v2.x, v2.y, v3.x, v3.y};
            *(float4*)yp       = o0;
            *(float4*)(yp + 4) = o1;
        }
        __syncthreads();
    }
#endif
}

// ======================= kernel 4: combine =======================
__global__ void combine_kernel(const float* __restrict__ b2, float* __restrict__ out) {
    int t = blockIdx.x;
    float w0 = g_wt[2 * t], w1 = g_wt[2 * t + 1];
    int s0 = g_slot[2 * t], s1 = g_slot[2 * t + 1];
    int e0 = g_eid[2 * t],  e1 = g_eid[2 * t + 1];
    int c = threadIdx.x * 4;
    float4 y0  = *(const float4*)(g_y + (size_t)s0 * ND + c);
    float4 y1  = *(const float4*)(g_y + (size_t)s1 * ND + c);
    float4 bb0 = *(const float4*)(b2 + (size_t)e0 * ND + c);
    float4 bb1 = *(const float4*)(b2 + (size_t)e1 * ND + c);
    float4 o;
    o.x = w0 * (y0.x + bb0.x) + w1 * (y1.x + bb1.x);
    o.y = w0 * (y0.y + bb0.y) + w1 * (y1.y + bb1.y);
    o.z = w0 * (y0.z + bb0.z) + w1 * (y1.z + bb1.z);
    o.w = w0 * (y0.w + bb0.w) + w1 * (y1.w + bb1.w);
    *(float4*)(out + (size_t)t * ND + c) = o;
}

// ======================= launch =======================
extern "C" void kernel_launch(void* const* d_in, const int* in_sizes, int n_in,
                              void* d_out, int out_size) {
    const float* x    = (const float*)d_in[0];
    const float* Wr   = (const float*)d_in[1];
    const float* temp = (const float*)d_in[2];
    const float* W1   = (const float*)d_in[3];
    const float* b1   = (const float*)d_in[4];
    const float* W2   = (const float*)d_in[5];
    const float* b2   = (const float*)d_in[6];
    float* out = (float*)d_out;

    cudaFuncSetAttribute(gemm1_tc, cudaFuncAttributeMaxDynamicSharedMemorySize, DYNSMEM);
    cudaFuncSetAttribute(gemm2_tc, cudaFuncAttributeMaxDynamicSharedMemorySize, DYNSMEM);

    zero_cnt_kernel<<<1, 32>>>();
    prep_w1<<<dim3(16, 64, NE), 128>>>(W1);
    prep_w2<<<dim3(32, 16, NE), 128>>>(W2);
    router_kernel<<<NT / 8, 256>>>(x, Wr, temp);
    // tcgen05 path (no-op bodies in a non-'a' cubin)
    gemm1_tc<<<dim3(NT / 128, NF / 128, NE), 256, DYNSMEM>>>(x, b1);
    // SIMT fallback (no-op bodies in the 'a' cubin)
    gemm1_simt<<<dim3(NT / 64, NF / 64), 256>>>(x, W1, b1);
    gemm2_tc<<<dim3(NT / 128, ND / 256, NE), 256, DYNSMEM>>>();
    gemm2_simt<<<dim3(NT / 64, ND / 128), 256>>>(W2);
    combine_kernel<<<NT, 256>>>(b2, out);
}

// round 6
// speedup vs baseline: 1.8469x; 1.8469x over previous
#include <cuda_runtime.h>
#include <cuda_bf16.h>
#include <cstdint>
#include <math.h>

#define NT 4096
#define ND 1024
#define NE 8
#define NF 2048
#define N2F 4096

// tcgen05 availability: only in the 'a'-suffix front-end passes
#if defined(__CUDA_ARCH_FEAT_SM103_ALL) || defined(__CUDA_ARCH_FEAT_SM100_ALL)
#define TC_OK 1
#else
#define TC_OK 0
#endif

typedef unsigned long long ull;

// ---------------- scratch (no allocs allowed) ----------------
__device__ int      g_cnt[NE];
__device__ int      g_tok[NE * NT];
__device__ float    g_wt[NT * 2];
__device__ int      g_slot[NT * 2];
__device__ int      g_eid[NT * 2];
__device__ uint32_t g_hidden_pk[(size_t)NE * NT * NF]; // tc: bf16 hi|lo pack; simt: fp32
__device__ float    g_y[(size_t)NE * NT * ND];

// ---------------- generic helpers ----------------
__device__ __forceinline__ uint32_t smem_u32(const void* p) {
    uint32_t a;
    asm("{ .reg .u64 t; cvta.to.shared.u64 t, %1; cvt.u32.u64 %0, t; }" : "=r"(a) : "l"(p));
    return a;
}
__device__ __forceinline__ uint32_t elect1() {
    uint32_t r;
    asm volatile("{ .reg .pred p; elect.sync _|p, 0xFFFFFFFF; selp.b32 %0,1,0,p; }" : "=r"(r));
    return r;
}
#define MBAR_INIT(a, c) asm volatile("mbarrier.init.shared.b64 [%0], %1;" :: "r"(a), "r"(c) : "memory")
#define MBAR_INVAL(a)   asm volatile("mbarrier.inval.shared.b64 [%0];" :: "r"(a) : "memory")
#define MBAR_WAIT(a, ph) do { uint32_t _m=(a); uint32_t _p=(ph); uint32_t _d;                               \
    asm volatile("{ .reg .pred p; mbarrier.try_wait.parity.acquire.cta.shared::cta.b64 p,[%1],%2; "        \
                 "selp.b32 %0,1,0,p; }" : "=r"(_d) : "r"(_m), "r"(_p) : "memory");                          \
    if (!_d) { asm volatile("{ .reg .pred P1; WL%=: "                                                      \
        "mbarrier.try_wait.parity.acquire.cta.shared::cta.b64 P1,[%0],%1,0x989680; "                       \
        "@P1 bra.uni WD%=; bra.uni WL%=; WD%=: }" :: "r"(_m), "r"(_p) : "memory"); } } while (0)
#define FENCE_ASYNC() asm volatile("fence.proxy.async.shared::cta;" ::: "memory")

// SW128 swizzle (tile-relative; tile bases 1024-aligned)
#define SWZ(x) ((x) ^ (((x) >> 3) & 0x70))

// ---------------- tcgen05-only macros/helpers ----------------
#if TC_OK
#define TCG_ALLOC(sa, n)  asm volatile("tcgen05.alloc.cta_group::1.sync.aligned.shared::cta.b32 [%0], %1;" :: "r"(sa), "r"(n) : "memory")
#define TCG_DEALLOC(t, n) asm volatile("tcgen05.dealloc.cta_group::1.sync.aligned.b32 %0, %1;" :: "r"(t), "r"(n))
#define TCG_RELINQ()      asm volatile("tcgen05.relinquish_alloc_permit.cta_group::1.sync.aligned;")
#define TCG_COMMIT(a)     asm volatile("tcgen05.commit.cta_group::1.mbarrier::arrive::one.shared::cluster.b64 [%0];" :: "r"(a) : "memory")
#define TCG_FENCE_AFTER()  asm volatile("tcgen05.fence::after_thread_sync;" ::: "memory")
#define TCG_FENCE_BEFORE() asm volatile("tcgen05.fence::before_thread_sync;" ::: "memory")
#define TCG_WAIT_LD()      asm volatile("tcgen05.wait::ld.sync.aligned;" ::: "memory")

#define TCG_LD32(r, ta) \
    asm volatile("tcgen05.ld.sync.aligned.32x32b.x32.b32 " \
        "{%0,%1,%2,%3,%4,%5,%6,%7,%8,%9,%10,%11,%12,%13,%14,%15," \
        "%16,%17,%18,%19,%20,%21,%22,%23,%24,%25,%26,%27,%28,%29,%30,%31}, [%32];" \
        : "=r"((r)[0]),"=r"((r)[1]),"=r"((r)[2]),"=r"((r)[3]),"=r"((r)[4]),"=r"((r)[5]),"=r"((r)[6]),"=r"((r)[7]), \
          "=r"((r)[8]),"=r"((r)[9]),"=r"((r)[10]),"=r"((r)[11]),"=r"((r)[12]),"=r"((r)[13]),"=r"((r)[14]),"=r"((r)[15]), \
          "=r"((r)[16]),"=r"((r)[17]),"=r"((r)[18]),"=r"((r)[19]),"=r"((r)[20]),"=r"((r)[21]),"=r"((r)[22]),"=r"((r)[23]), \
          "=r"((r)[24]),"=r"((r)[25]),"=r"((r)[26]),"=r"((r)[27]),"=r"((r)[28]),"=r"((r)[29]),"=r"((r)[30]),"=r"((r)[31]) \
        : "r"(ta))

__device__ __forceinline__ uint64_t descK(uint32_t a) {   // K-major SW128: LBO=1, SBO=64
    return ((uint64_t)2 << 61) | ((uint64_t)1 << 46) | ((uint64_t)64 << 32) |
           ((uint64_t)1 << 16) | ((a >> 4) & 0x3FFF);
}
// kind::f16 idesc: dtype=F32, atype=btype=BF16, both K-major, N=64, M=128
#define IDESC_BF16 ((1u<<4) | (1u<<7) | (1u<<10) | (8u<<17) | (8u<<24))

__device__ __forceinline__ void mma_bf16(uint32_t d, uint64_t ad, uint64_t bd, uint32_t en) {
    asm volatile("{ .reg .pred p; setp.ne.u32 p, %4, 0;\n\t"
        "tcgen05.mma.cta_group::1.kind::f16 [%0], %1, %2, %3, {%5,%5,%5,%5}, p; }"
        :: "r"(d), "l"(ad), "l"(bd), "r"(IDESC_BF16), "r"(en), "r"(0u) : "memory");
}
#endif // TC_OK

// pack two fp32 -> bf16x2 (h -> high half, l -> low half)
__device__ __forceinline__ uint32_t bf2(float h, float l) {
    uint32_t r; asm("cvt.rn.bf16x2.f32 %0, %1, %2;" : "=r"(r) : "f"(h), "f"(l)); return r;
}
// split 8 fp32 into hi(trunc top-16, exact bf16) and lo(bf16_rn of residual)
__device__ __forceinline__ void split8(float4 v0, float4 v1, uint4& hi, uint4& lo) {
    uint32_t u0 = __float_as_uint(v0.x), u1 = __float_as_uint(v0.y);
    uint32_t u2 = __float_as_uint(v0.z), u3 = __float_as_uint(v0.w);
    uint32_t u4 = __float_as_uint(v1.x), u5 = __float_as_uint(v1.y);
    uint32_t u6 = __float_as_uint(v1.z), u7 = __float_as_uint(v1.w);
    hi.x = __byte_perm(u0, u1, 0x7632); hi.y = __byte_perm(u2, u3, 0x7632);
    hi.z = __byte_perm(u4, u5, 0x7632); hi.w = __byte_perm(u6, u7, 0x7632);
    float l0 = v0.x - __uint_as_float(u0 & 0xffff0000u);
    float l1 = v0.y - __uint_as_float(u1 & 0xffff0000u);
    float l2 = v0.z - __uint_as_float(u2 & 0xffff0000u);
    float l3 = v0.w - __uint_as_float(u3 & 0xffff0000u);
    float l4 = v1.x - __uint_as_float(u4 & 0xffff0000u);
    float l5 = v1.y - __uint_as_float(u5 & 0xffff0000u);
    float l6 = v1.z - __uint_as_float(u6 & 0xffff0000u);
    float l7 = v1.w - __uint_as_float(u7 & 0xffff0000u);
    lo.x = bf2(l1, l0); lo.y = bf2(l3, l2); lo.z = bf2(l5, l4); lo.w = bf2(l7, l6);
}

// packed f32x2 (SIMT fallback)
__device__ __forceinline__ ull packf2(float x, float y) {
    ull u; asm("mov.b64 %0,{%1,%2};" : "=l"(u) : "f"(x), "f"(y)); return u;
}
__device__ __forceinline__ float2 unpk(ull u) {
    float2 r; asm("mov.b64 {%0,%1},%2;" : "=f"(r.x), "=f"(r.y) : "l"(u)); return r;
}
__device__ __forceinline__ ull fma2(ull a, ull b, ull c) {
    ull d; asm("fma.rn.f32x2 %0, %1, %2, %3;" : "=l"(d) : "l"(a), "l"(b), "l"(c)); return d;
}

// SMEM layout (after 1024-aligned data0):
//   A (single buffer, 2 M-tiles): tile t: AHI @ t*32768, ALO @ t*32768+16384   (64 KB)
//   B (double buffer): stage s @ 65536 + s*65536; BHI @ +0, BLO @ +32768      (128 KB)
#define OFF_B    65536
#define DYNSMEM  198656

// ======================= kernel 0: zero counters =======================
__global__ void zero_cnt_kernel() {
    if (threadIdx.x < NE) g_cnt[threadIdx.x] = 0;
}

// ======================= kernel 1: router (float4 x loads) =======================
__global__ void router_kernel(const float* __restrict__ x,
                              const float* __restrict__ Wr,
                              const float* __restrict__ temp) {
    int t    = (blockIdx.x * blockDim.x + threadIdx.x) >> 5;
    int lane = threadIdx.x & 31;
    if (t >= NT) return;
    const float4* xr = (const float4*)(x + (size_t)t * ND);
    const float4* wr4 = (const float4*)Wr;
    float acc[NE];
#pragma unroll
    for (int e = 0; e < NE; e++) acc[e] = 0.f;
    for (int d4 = lane; d4 < ND / 4; d4 += 32) {
        float4 xv = xr[d4];
        float xs[4] = {xv.x, xv.y, xv.z, xv.w};
#pragma unroll
        for (int j = 0; j < 4; j++) {
            int d = 4 * d4 + j;
            float4 w0 = wr4[d * 2], w1 = wr4[d * 2 + 1];
            acc[0] = fmaf(xs[j], w0.x, acc[0]);
            acc[1] = fmaf(xs[j], w0.y, acc[1]);
            acc[2] = fmaf(xs[j], w0.z, acc[2]);
            acc[3] = fmaf(xs[j], w0.w, acc[3]);
            acc[4] = fmaf(xs[j], w1.x, acc[4]);
            acc[5] = fmaf(xs[j], w1.y, acc[5]);
            acc[6] = fmaf(xs[j], w1.z, acc[6]);
            acc[7] = fmaf(xs[j], w1.w, acc[7]);
        }
    }
#pragma unroll
    for (int e = 0; e < NE; e++) {
#pragma unroll
        for (int off = 16; off > 0; off >>= 1)
            acc[e] += __shfl_xor_sync(0xffffffffu, acc[e], off);
    }
    if (lane == 0) {
        float ti = 1.0f / temp[0];
#pragma unroll
        for (int e = 0; e < NE; e++) acc[e] *= ti;
        int i0 = 0; float l0 = acc[0];
#pragma unroll
        for (int e = 1; e < NE; e++) if (acc[e] > l0) { l0 = acc[e]; i0 = e; }
        int i1 = -1; float l1 = -3.4e38f;
#pragma unroll
        for (int e = 0; e < NE; e++)
            if (e != i0 && acc[e] > l1) { l1 = acc[e]; i1 = e; }
        float ex  = expf(l1 - l0);
        float w1v = ex / (1.f + ex);
        float w0v = 1.f - w1v;
        int p0 = atomicAdd(&g_cnt[i0], 1);
        int p1 = atomicAdd(&g_cnt[i1], 1);
        g_tok[i0 * NT + p0] = t;
        g_tok[i1 * NT + p1] = t;
        g_slot[2 * t]     = i0 * NT + p0;
        g_slot[2 * t + 1] = i1 * NT + p1;
        g_wt[2 * t]     = w0v;
        g_wt[2 * t + 1] = w1v;
        g_eid[2 * t]     = i0;
        g_eid[2 * t + 1] = i1;
    }
}

// ======================= tcgen05 GEMM1 + SwiGLU =======================
// M = 256 (two 128-row MMA tiles sharing B); N: 128 a + 128 g; K=1024, 16 chunks of 64.
__global__ __launch_bounds__(256, 1) void gemm1_tc(
        const float* __restrict__ x,
        const float* __restrict__ W1,
        const float* __restrict__ b1) {
#if TC_OK
    int e    = blockIdx.z;
    int cnt  = g_cnt[e];
    int row0 = blockIdx.x * 256;
    if (row0 >= cnt) return;
    int na0 = blockIdx.y * 128;

    extern __shared__ char dynsmem[];
    uint32_t raw   = smem_u32(dynsmem);
    uint32_t base  = (raw + 1023) & ~1023u;
    uint32_t hdr   = base;
    uint32_t data0 = base + 1024;
    char* pdata = dynsmem + (data0 - raw);

    int tid = threadIdx.x, wid = tid >> 5, lane = tid & 31;

    if (tid == 0) { MBAR_INIT(hdr + 8, 1); MBAR_INIT(hdr + 16, 1); }
    if (wid == 0) { TCG_ALLOC(hdr, 512); }
    __syncthreads();
    uint32_t tmem;
    asm("ld.shared.b32 %0, [%1];" : "=r"(tmem) : "r"(hdr));

    // A gather: each thread handles half-rows (r0, kh) of tiles 0 and 1
    int r0 = tid >> 1, kh = tid & 1;
    const float* ap[2];
    {
        int rr0 = row0 + r0;        if (rr0 >= cnt) rr0 = cnt - 1;
        int rr1 = row0 + 128 + r0;  if (rr1 >= cnt) rr1 = cnt - 1;
        ap[0] = x + (size_t)g_tok[e * NT + rr0] * ND + kh * 32;
        ap[1] = x + (size_t)g_tok[e * NT + rr1] * ND + kh * 32;
    }
    // B: one column per thread (256 cols: 128 a + 128 g)
    int bs = tid >> 6, bcc = tid & 63;
    const float* bcol = W1 + (size_t)e * ND * N2F +
        ((tid < 128) ? (size_t)(na0 + tid) : ((size_t)NF + na0 + (tid - 128)));

    const int CH = ND / 64; // 16
    for (int c = 0; c < CH; c++) {
        int b = c & 1;
        int k0 = c * 64;
        // 1. prefetch A into registers (no SMEM hazard yet)
        float4 av[2][8];
#pragma unroll
        for (int t = 0; t < 2; t++) {
            const float4* p = (const float4*)(ap[t] + k0);
#pragma unroll
            for (int j = 0; j < 8; j++) av[t][j] = p[j];
        }
        // 2. B stage free (commit of chunk c-2)
        if (c >= 2) MBAR_WAIT(hdr + 8 + 8 * b, ((c - 2) >> 1) & 1);
        // 3. B fill stage b (overlaps MMA(c-1))
        {
            char* sb = pdata + OFF_B + b * 65536;
            const float* gc = bcol + (size_t)k0 * N2F;
#pragma unroll
            for (int kb = 0; kb < 8; kb++) {
                float4 v0, v1;
                v0.x = gc[(size_t)(kb * 8 + 0) * N2F];
                v0.y = gc[(size_t)(kb * 8 + 1) * N2F];
                v0.z = gc[(size_t)(kb * 8 + 2) * N2F];
                v0.w = gc[(size_t)(kb * 8 + 3) * N2F];
                v1.x = gc[(size_t)(kb * 8 + 4) * N2F];
                v1.y = gc[(size_t)(kb * 8 + 5) * N2F];
                v1.z = gc[(size_t)(kb * 8 + 6) * N2F];
                v1.w = gc[(size_t)(kb * 8 + 7) * N2F];
                uint4 hi, lo; split8(v0, v1, hi, lo);
                uint32_t off = bs * 8192 + SWZ((uint32_t)(bcc * 128 + kb * 16));
                *(uint4*)(sb + off)         = hi;
                *(uint4*)(sb + 32768 + off) = lo;
            }
        }
        // 4. A buffer free (commit of chunk c-1)
        if (c >= 1) MBAR_WAIT(hdr + 8 + 8 * ((c - 1) & 1), ((c - 1) >> 1) & 1);
        // 5. A split + store
#pragma unroll
        for (int t = 0; t < 2; t++) {
            char* sa = pdata + t * 32768;
#pragma unroll
            for (int i = 0; i < 4; i++) {
                uint4 hi, lo; split8(av[t][2 * i], av[t][2 * i + 1], hi, lo);
                uint32_t off = SWZ((uint32_t)(r0 * 128 + kh * 64 + i * 16));
                *(uint4*)(sa + off)         = hi;
                *(uint4*)(sa + 16384 + off) = lo;
            }
        }
        FENCE_ASYNC();
        __syncthreads();
        // 6. issue 96 MMAs (3 precision passes x 4 ks x 2 tiles x 4 nt)
        if (wid == 0 && elect1()) {
            uint32_t stB = data0 + OFF_B + b * 65536;
            uint64_t aHi[2] = { descK(data0),         descK(data0 + 32768) };
            uint64_t aLo[2] = { descK(data0 + 16384), descK(data0 + 49152) };
#pragma unroll
            for (int pi = 0; pi < 3; pi++) {
                uint32_t bPl = (pi == 1) ? 32768u : 0u;
#pragma unroll
                for (int ks = 0; ks < 4; ks++) {
                    uint32_t en = (c > 0 || pi > 0 || ks > 0) ? 1u : 0u;
#pragma unroll
                    for (int t = 0; t < 2; t++) {
                        uint64_t ad = ((pi == 2) ? aLo[t] : aHi[t]) + (uint64_t)(ks * 2);
#pragma unroll
                        for (int nt = 0; nt < 4; nt++) {
                            uint64_t bd = descK(stB + bPl + nt * 8192) + (uint64_t)(ks * 2);
                            mma_bf16(tmem + t * 256 + nt * 64, ad, bd, en);
                        }
                    }
                }
            }
            TCG_COMMIT(hdr + 8 + 8 * b);
        }
    }
    MBAR_WAIT(hdr + 8 + 8 * ((CH - 1) & 1), ((CH - 1) >> 1) & 1);
    TCG_FENCE_AFTER();
    // epilogue: warps 0-3 -> tile0, warps 4-7 -> tile1
    int tl = wid >> 2;
    int row = row0 + tl * 128 + (wid & 3) * 32 + lane;
    bool act = row < cnt;
    const float* b1a = b1 + (size_t)e * N2F + na0;
    const float* b1g = b1 + (size_t)e * N2F + NF + na0;
    for (int j = 0; j < 4; j++) {
        uint32_t ar[32], gr[32];
        TCG_LD32(ar, tmem + tl * 256 + j * 32);
        TCG_LD32(gr, tmem + tl * 256 + 128 + j * 32);
        TCG_WAIT_LD();
        if (act) {
            uint32_t pk[32];
#pragma unroll
            for (int q = 0; q < 32; q++) {
                float avv = __uint_as_float(ar[q]) + b1a[j * 32 + q];
                float gvv = __uint_as_float(gr[q]) + b1g[j * 32 + q];
                float hv = avv * (gvv / (1.f + __expf(-gvv)));
                uint32_t u = __float_as_uint(hv);
                float lof = hv - __uint_as_float(u & 0xffff0000u);
                uint16_t lob = __bfloat16_as_ushort(__float2bfloat16(lof));
                pk[q] = (u >> 16) | ((uint32_t)lob << 16);
            }
            uint32_t* dst = g_hidden_pk + ((size_t)e * NT + row) * NF + na0 + j * 32;
#pragma unroll
            for (int q = 0; q < 8; q++) *(uint4*)(dst + 4 * q) = *(uint4*)&pk[4 * q];
        }
    }
    TCG_FENCE_BEFORE();
    __syncthreads();
    if (tid == 0) { MBAR_INVAL(hdr + 8); MBAR_INVAL(hdr + 16); }
    if (wid == 0) { TCG_RELINQ(); TCG_DEALLOC(tmem, 512); }
#endif
}

// ======================= tcgen05 GEMM2 =======================
// M = 256 (two tiles); N-tile 256 of d_model; K=2048, 32 chunks of 64.
__global__ __launch_bounds__(256, 1) void gemm2_tc(const float* __restrict__ W2) {
#if TC_OK
    int e    = blockIdx.z;
    int cnt  = g_cnt[e];
    int row0 = blockIdx.x * 256;
    if (row0 >= cnt) return;
    int n0 = blockIdx.y * 256;

    extern __shared__ char dynsmem[];
    uint32_t raw   = smem_u32(dynsmem);
    uint32_t base  = (raw + 1023) & ~1023u;
    uint32_t hdr   = base;
    uint32_t data0 = base + 1024;
    char* pdata = dynsmem + (data0 - raw);

    int tid = threadIdx.x, wid = tid >> 5, lane = tid & 31;

    if (tid == 0) { MBAR_INIT(hdr + 8, 1); MBAR_INIT(hdr + 16, 1); }
    if (wid == 0) { TCG_ALLOC(hdr, 512); }
    __syncthreads();
    uint32_t tmem;
    asm("ld.shared.b32 %0, [%1];" : "=r"(tmem) : "r"(hdr));

    int r0 = tid >> 1, kh = tid & 1;
    const uint32_t* hp[2];
    {
        int rr0 = row0 + r0;        if (rr0 >= cnt) rr0 = cnt - 1;
        int rr1 = row0 + 128 + r0;  if (rr1 >= cnt) rr1 = cnt - 1;
        hp[0] = g_hidden_pk + ((size_t)e * NT + rr0) * NF + kh * 32;
        hp[1] = g_hidden_pk + ((size_t)e * NT + rr1) * NF + kh * 32;
    }
    int bs = tid >> 6, bcc = tid & 63;
    const float* bcol = W2 + (size_t)e * NF * ND + n0 + tid;

    const int CH = NF / 64; // 32
    for (int c = 0; c < CH; c++) {
        int b = c & 1;
        int k0 = c * 64;
        // 1. prefetch A (packed hidden) into registers
        uint4 aw[2][8];
#pragma unroll
        for (int t = 0; t < 2; t++) {
            const uint4* p = (const uint4*)(hp[t] + k0);
#pragma unroll
            for (int j = 0; j < 8; j++) aw[t][j] = p[j];
        }
        // 2. B stage free
        if (c >= 2) MBAR_WAIT(hdr + 8 + 8 * b, ((c - 2) >> 1) & 1);
        // 3. B fill
        {
            char* sb = pdata + OFF_B + b * 65536;
            const float* gc = bcol + (size_t)k0 * ND;
#pragma unroll
            for (int kb = 0; kb < 8; kb++) {
                float4 v0, v1;
                v0.x = gc[(size_t)(kb * 8 + 0) * ND];
                v0.y = gc[(size_t)(kb * 8 + 1) * ND];
                v0.z = gc[(size_t)(kb * 8 + 2) * ND];
                v0.w = gc[(size_t)(kb * 8 + 3) * ND];
                v1.x = gc[(size_t)(kb * 8 + 4) * ND];
                v1.y = gc[(size_t)(kb * 8 + 5) * ND];
                v1.z = gc[(size_t)(kb * 8 + 6) * ND];
                v1.w = gc[(size_t)(kb * 8 + 7) * ND];
                uint4 hi, lo; split8(v0, v1, hi, lo);
                uint32_t off = bs * 8192 + SWZ((uint32_t)(bcc * 128 + kb * 16));
                *(uint4*)(sb + off)         = hi;
                *(uint4*)(sb + 32768 + off) = lo;
            }
        }
        // 4. A buffer free
        if (c >= 1) MBAR_WAIT(hdr + 8 + 8 * ((c - 1) & 1), ((c - 1) >> 1) & 1);
        // 5. A unpack + store
#pragma unroll
        for (int t = 0; t < 2; t++) {
            char* sa = pdata + t * 32768;
#pragma unroll
            for (int i = 0; i < 4; i++) {
                uint4 w0 = aw[t][2 * i], w1 = aw[t][2 * i + 1];
                uint4 hi, lo;
                hi.x = __byte_perm(w0.x, w0.y, 0x5410); lo.x = __byte_perm(w0.x, w0.y, 0x7632);
                hi.y = __byte_perm(w0.z, w0.w, 0x5410); lo.y = __byte_perm(w0.z, w0.w, 0x7632);
                hi.z = __byte_perm(w1.x, w1.y, 0x5410); lo.z = __byte_perm(w1.x, w1.y, 0x7632);
                hi.w = __byte_perm(w1.z, w1.w, 0x5410); lo.w = __byte_perm(w1.z, w1.w, 0x7632);
                uint32_t off = SWZ((uint32_t)(r0 * 128 + kh * 64 + i * 16));
                *(uint4*)(sa + off)         = hi;
                *(uint4*)(sa + 16384 + off) = lo;
            }
        }
        FENCE_ASYNC();
        __syncthreads();
        if (wid == 0 && elect1()) {
            uint32_t stB = data0 + OFF_B + b * 65536;
            uint64_t aHi[2] = { descK(data0),         descK(data0 + 32768) };
            uint64_t aLo[2] = { descK(data0 + 16384), descK(data0 + 49152) };
#pragma unroll
            for (int pi = 0; pi < 3; pi++) {
                uint32_t bPl = (pi == 1) ? 32768u : 0u;
#pragma unroll
                for (int ks = 0; ks < 4; ks++) {
                    uint32_t en = (c > 0 || pi > 0 || ks > 0) ? 1u : 0u;
#pragma unroll
                    for (int t = 0; t < 2; t++) {
                        uint64_t ad = ((pi == 2) ? aLo[t] : aHi[t]) + (uint64_t)(ks * 2);
#pragma unroll
                        for (int nt = 0; nt < 4; nt++) {
                            uint64_t bd = descK(stB + bPl + nt * 8192) + (uint64_t)(ks * 2);
                            mma_bf16(tmem + t * 256 + nt * 64, ad, bd, en);
                        }
                    }
                }
            }
            TCG_COMMIT(hdr + 8 + 8 * b);
        }
    }
    MBAR_WAIT(hdr + 8 + 8 * ((CH - 1) & 1), ((CH - 1) >> 1) & 1);
    TCG_FENCE_AFTER();
    int tl = wid >> 2;
    int row = row0 + tl * 128 + (wid & 3) * 32 + lane;
    bool act = row < cnt;
    for (int j = 0; j < 8; j++) {
        uint32_t yr[32];
        TCG_LD32(yr, tmem + tl * 256 + j * 32);
        TCG_WAIT_LD();
        if (act) {
            float* dst = g_y + ((size_t)e * NT + row) * ND + n0 + j * 32;
#pragma unroll
            for (int q = 0; q < 8; q++) *(uint4*)(dst + 4 * q) = *(uint4*)&yr[4 * q];
        }
    }
    TCG_FENCE_BEFORE();
    __syncthreads();
    if (tid == 0) { MBAR_INVAL(hdr + 8); MBAR_INVAL(hdr + 16); }
    if (wid == 0) { TCG_RELINQ(); TCG_DEALLOC(tmem, 512); }
#endif
}

// ======================= SIMT fallback GEMM1 + SwiGLU (expert loop inside) =======================
__global__ __launch_bounds__(256) void gemm1_simt(
        const float* __restrict__ x,
        const float* __restrict__ W1,
        const float* __restrict__ b1) {
#if !TC_OK
    __shared__ __align__(16) float As[64][16];
    __shared__ __align__(16) float BsA[16][64];
    __shared__ __align__(16) float BsG[16][64];
    int row0 = blockIdx.x * 64;
    int col0 = blockIdx.y * 64;
    int tid = threadIdx.x;
    int tx = tid & 15, ty = tid >> 4;
    int ra = tid >> 2, qa = tid & 3;
    int kb = tid >> 4, qb = tid & 15;

    for (int e = 0; e < NE; e++) {
        int cnt = g_cnt[e];
        if (row0 >= cnt) continue;
        int rowa = row0 + ra;
        if (rowa >= cnt) rowa = cnt - 1;
        int tok = g_tok[e * NT + rowa];
        const float* xrow = x + (size_t)tok * ND;
        const float* W1e = W1 + (size_t)e * ND * N2F;

        ull accA[4][2], accG[4][2];
#pragma unroll
        for (int r = 0; r < 4; r++)
#pragma unroll
            for (int c = 0; c < 2; c++) { accA[r][c] = 0ull; accG[r][c] = 0ull; }

        for (int k0 = 0; k0 < ND; k0 += 16) {
            float4 av = *(const float4*)(xrow + k0 + qa * 4);
            const float* brow = W1e + (size_t)(k0 + kb) * N2F + col0;
            float4 bA = *(const float4*)(brow + qb * 4);
            float4 bG = *(const float4*)(brow + NF + qb * 4);
            __syncthreads();
            *(float4*)&As[ra][qa * 4]  = av;
            *(float4*)&BsA[kb][qb * 4] = bA;
            *(float4*)&BsG[kb][qb * 4] = bG;
            __syncthreads();
#pragma unroll
            for (int kk = 0; kk < 16; kk++) {
                float4 fA = *(const float4*)&BsA[kk][tx * 4];
                float4 fG = *(const float4*)&BsG[kk][tx * 4];
                ull bA0 = packf2(fA.x, fA.y), bA1 = packf2(fA.z, fA.w);
                ull bG0 = packf2(fG.x, fG.y), bG1 = packf2(fG.z, fG.w);
#pragma unroll
                for (int r = 0; r < 4; r++) {
                    float a = As[ty * 4 + r][kk];
                    ull aa = packf2(a, a);
                    accA[r][0] = fma2(aa, bA0, accA[r][0]);
                    accA[r][1] = fma2(aa, bA1, accA[r][1]);
                    accG[r][0] = fma2(aa, bG0, accG[r][0]);
                    accG[r][1] = fma2(aa, bG1, accG[r][1]);
                }
            }
        }
        float bvA[4], bvG[4];
#pragma unroll
        for (int c = 0; c < 4; c++) {
            bvA[c] = b1[(size_t)e * N2F + col0 + tx * 4 + c];
            bvG[c] = b1[(size_t)e * N2F + NF + col0 + tx * 4 + c];
        }
        float* ghid = (float*)g_hidden_pk;
#pragma unroll
        for (int r = 0; r < 4; r++) {
            int row = row0 + ty * 4 + r;
            if (row >= cnt) continue;
            float2 a0 = unpk(accA[r][0]), a1 = unpk(accA[r][1]);
            float2 g0 = unpk(accG[r][0]), g1 = unpk(accG[r][1]);
            float avv[4] = {a0.x, a0.y, a1.x, a1.y};
            float gvv[4] = {g0.x, g0.y, g1.x, g1.y};
            float4 hout; float* hp2 = (float*)&hout;
#pragma unroll
            for (int c = 0; c < 4; c++) {
                float aval = avv[c] + bvA[c];
                float gval = gvv[c] + bvG[c];
                hp2[c] = aval * (gval / (1.f + expf(-gval)));
            }
            *(float4*)(ghid + ((size_t)e * NT + row) * NF + col0 + tx * 4) = hout;
        }
        __syncthreads();
    }
#endif
}

// ======================= SIMT fallback GEMM2 (expert loop inside) =======================
__global__ __launch_bounds__(256) void gemm2_simt(const float* __restrict__ W2) {
#if !TC_OK
    __shared__ __align__(16) float As[64][16];
    __shared__ __align__(16) float Bs[16][128];
    int row0 = blockIdx.x * 64;
    int col0 = blockIdx.y * 128;
    int tid = threadIdx.x;
    int tx = tid & 15, ty = tid >> 4;
    int ra = tid >> 2, qa = tid & 3;
    int s0i = tid,       kb0 = s0i >> 5, qb0 = s0i & 31;
    int s1i = tid + 256, kb1 = s1i >> 5, qb1 = s1i & 31;

    for (int e = 0; e < NE; e++) {
        int cnt = g_cnt[e];
        if (row0 >= cnt) continue;
        int rowa = row0 + ra;
        if (rowa >= cnt) rowa = cnt - 1;
        const float* ghid = (const float*)g_hidden_pk;
        const float* hrow = ghid + ((size_t)e * NT + rowa) * NF;
        const float* W2e  = W2 + (size_t)e * NF * ND;

        ull acc[4][4];
#pragma unroll
        for (int r = 0; r < 4; r++)
#pragma unroll
            for (int c = 0; c < 4; c++) acc[r][c] = 0ull;

        for (int k0 = 0; k0 < NF; k0 += 16) {
            float4 av  = *(const float4*)(hrow + k0 + qa * 4);
            float4 bv0 = *(const float4*)(W2e + (size_t)(k0 + kb0) * ND + col0 + qb0 * 4);
            float4 bv1 = *(const float4*)(W2e + (size_t)(k0 + kb1) * ND + col0 + qb1 * 4);
            __syncthreads();
            *(float4*)&As[ra][qa * 4]   = av;
            *(float4*)&Bs[kb0][qb0 * 4] = bv0;
            *(float4*)&Bs[kb1][qb1 * 4] = bv1;
            __syncthreads();
#pragma unroll
            for (int kk = 0; kk < 16; kk++) {
                float4 f0 = *(const float4*)&Bs[kk][tx * 8];
                float4 f1 = *(const float4*)&Bs[kk][tx * 8 + 4];
                ull b0 = packf2(f0.x, f0.y), b1p = packf2(f0.z, f0.w);
                ull b2p = packf2(f1.x, f1.y), b3p = packf2(f1.z, f1.w);
#pragma unroll
                for (int r = 0; r < 4; r++) {
                    float a = As[ty * 4 + r][kk];
                    ull aa = packf2(a, a);
                    acc[r][0] = fma2(aa, b0,  acc[r][0]);
                    acc[r][1] = fma2(aa, b1p, acc[r][1]);
                    acc[r][2] = fma2(aa, b2p, acc[r][2]);
                    acc[r][3] = fma2(aa, b3p, acc[r][3]);
                }
            }
        }
#pragma unroll
        for (int r = 0; r < 4; r++) {
            int row = row0 + ty * 4 + r;
            if (row >= cnt) continue;
            float* yp = g_y + ((size_t)e * NT + row) * ND + col0 + tx * 8;
            float2 v0 = unpk(acc[r][0]), v1 = unpk(acc[r][1]);
            float2 v2 = unpk(acc[r][2]), v3 = unpk(acc[r][3]);
            float4 o0 = {v0.x, v0.y, v1.x, v1.y};
            float4 o1 = {v2.x, v2.y, v3.x, v3.y};
            *(float4*)yp       = o0;
            *(float4*)(yp + 4) = o1;
        }
        __syncthreads();
    }
#endif
}

// ======================= kernel 4: combine =======================
__global__ void combine_kernel(const float* __restrict__ b2, float* __restrict__ out) {
    int t = blockIdx.x;
    float w0 = g_wt[2 * t], w1 = g_wt[2 * t + 1];
    int s0 = g_slot[2 * t], s1 = g_slot[2 * t + 1];
    int e0 = g_eid[2 * t],  e1 = g_eid[2 * t + 1];
    int c = threadIdx.x * 4;
    float4 y0  = *(const float4*)(g_y + (size_t)s0 * ND + c);
    float4 y1  = *(const float4*)(g_y + (size_t)s1 * ND + c);
    float4 bb0 = *(const float4*)(b2 + (size_t)e0 * ND + c);
    float4 bb1 = *(const float4*)(b2 + (size_t)e1 * ND + c);
    float4 o;
    o.x = w0 * (y0.x + bb0.x) + w1 * (y1.x + bb1.x);
    o.y = w0 * (y0.y + bb0.y) + w1 * (y1.y + bb1.y);
    o.z = w0 * (y0.z + bb0.z) + w1 * (y1.z + bb1.z);
    o.w = w0 * (y0.w + bb0.w) + w1 * (y1.w + bb1.w);
    *(float4*)(out + (size_t)t * ND + c) = o;
}

// ======================= launch =======================
extern "C" void kernel_launch(void* const* d_in, const int* in_sizes, int n_in,
                              void* d_out, int out_size) {
    const float* x    = (const float*)d_in[0];
    const float* Wr   = (const float*)d_in[1];
    const float* temp = (const float*)d_in[2];
    const float* W1   = (const float*)d_in[3];
    const float* b1   = (const float*)d_in[4];
    const float* W2   = (const float*)d_in[5];
    const float* b2   = (const float*)d_in[6];
    float* out = (float*)d_out;

    cudaFuncSetAttribute(gemm1_tc, cudaFuncAttributeMaxDynamicSharedMemorySize, DYNSMEM);
    cudaFuncSetAttribute(gemm2_tc, cudaFuncAttributeMaxDynamicSharedMemorySize, DYNSMEM);

    zero_cnt_kernel<<<1, 32>>>();
    router_kernel<<<NT / 8, 256>>>(x, Wr, temp);
    // tcgen05 path (no-op bodies in a non-'a' cubin)
    gemm1_tc<<<dim3(NT / 256, NF / 128, NE), 256, DYNSMEM>>>(x, W1, b1);
    // SIMT fallback (no-op bodies in the 'a' cubin)
    gemm1_simt<<<dim3(NT / 64, NF / 64), 256>>>(x, W1, b1);
    gemm2_tc<<<dim3(NT / 256, ND / 256, NE), 256, DYNSMEM>>>(W2);
    gemm2_simt<<<dim3(NT / 64, ND / 128), 256>>>(W2);
    combine_kernel<<<NT, 256>>>(b2, out);
}